// round 1
// baseline (speedup 1.0000x reference)
#include <cuda_runtime.h>
#include <cuda_bf16.h>
#include <cstddef>

// ---------------------------------------------------------------------------
// GCN: 4x GraphConv (agg = adj@h ; out = relu([h|agg]@W + b)) + MLP classifier
// B=32, N=1024, D=256, NHID=512, NHID_HALF=256, NCLASS=2
// ---------------------------------------------------------------------------

#define MAXELEM (32 * 1024 * 512)  // 16,777,216 floats = 64 MB

__device__ float g_agg[MAXELEM];
__device__ float g_h0[MAXELEM];
__device__ float g_h1[MAXELEM];

// ---------------------------------------------------------------------------
// Generic 128x128 tiled fp32 GEMM, 256 threads, 8x8 microtile, double-buffered.
//   C[bz] = epi( A[bz] @ Bm[bz] + bias )
// A is a virtual [M,K] matrix split at ksplit along K:
//   k <  ksplit : A0 (leading dim = ksplit)
//   k >= ksplit : A1 (leading dim = K - ksplit)
// (set ksplit==K for a single-operand GEMM)
// EPI: 0 = none, 1 = bias+relu, 2 = bias+prelu(alpha)
// Requires: M%128==0, N%128==0, K%8==0, ksplit%8==0.
// ---------------------------------------------------------------------------
template <int EPI>
__global__ void __launch_bounds__(256, 2)
gemm_kernel(const float* __restrict__ A0, const float* __restrict__ A1, int ksplit,
            const float* __restrict__ Bm, const float* __restrict__ bias,
            const float* __restrict__ alpha, float* __restrict__ C,
            int M, int N, int K,
            long sA, long sB, long sC)
{
    __shared__ float As[2][8][128];
    __shared__ float Bs[2][8][128];

    const int tid = threadIdx.x;
    const int bz = blockIdx.z;
    const float* A0b = A0 + (size_t)bz * sA;
    const float* A1b = A1 + (size_t)bz * sA;
    const float* Bb  = Bm + (size_t)bz * sB;
    float*       Cb  = C  + (size_t)bz * sC;

    const int row0 = blockIdx.y * 128;
    const int col0 = blockIdx.x * 128;

    // A-tile load: thread -> (row, 4 consecutive k)
    const int arow  = row0 + (tid >> 1);
    const int akoff = (tid & 1) * 4;
    // B-tile load: thread -> (k-row, 4 consecutive cols)
    const int bkoff = tid >> 5;
    const int bcol  = col0 + (tid & 31) * 4;

    const int lda1 = K - ksplit;

    float4 aReg, bReg;

#define FETCH_A(k0)                                                              \
    do {                                                                         \
        int kg = (k0) + akoff;                                                   \
        const float* p = (kg < ksplit)                                           \
            ? (A0b + (size_t)arow * ksplit + kg)                                 \
            : (A1b + (size_t)arow * lda1 + (kg - ksplit));                       \
        aReg = *reinterpret_cast<const float4*>(p);                              \
    } while (0)

#define FETCH_B(k0)                                                              \
    bReg = *reinterpret_cast<const float4*>(Bb + (size_t)((k0) + bkoff) * N + bcol)

#define STORE_A(buf)                                                             \
    do {                                                                         \
        As[buf][akoff + 0][tid >> 1] = aReg.x;                                   \
        As[buf][akoff + 1][tid >> 1] = aReg.y;                                   \
        As[buf][akoff + 2][tid >> 1] = aReg.z;                                   \
        As[buf][akoff + 3][tid >> 1] = aReg.w;                                   \
    } while (0)

#define STORE_B(buf)                                                             \
    *reinterpret_cast<float4*>(&Bs[buf][bkoff][(tid & 31) * 4]) = bReg

    float acc[8][8];
#pragma unroll
    for (int i = 0; i < 8; i++)
#pragma unroll
        for (int j = 0; j < 8; j++) acc[i][j] = 0.0f;

    FETCH_A(0);
    FETCH_B(0);
    STORE_A(0);
    STORE_B(0);
    __syncthreads();

    const int ty = tid >> 4;
    const int tx = tid & 15;
    const int nk = K >> 3;

    for (int kt = 0; kt < nk; kt++) {
        const int cur = kt & 1;
        if (kt + 1 < nk) {
            FETCH_A((kt + 1) * 8);
            FETCH_B((kt + 1) * 8);
        }
#pragma unroll
        for (int kk = 0; kk < 8; kk++) {
            float a[8], b[8];
#pragma unroll
            for (int i = 0; i < 8; i++) a[i] = As[cur][kk][ty * 8 + i];
#pragma unroll
            for (int j = 0; j < 8; j++) b[j] = Bs[cur][kk][tx * 8 + j];
#pragma unroll
            for (int i = 0; i < 8; i++)
#pragma unroll
                for (int j = 0; j < 8; j++)
                    acc[i][j] = fmaf(a[i], b[j], acc[i][j]);
        }
        if (kt + 1 < nk) {
            STORE_A(cur ^ 1);
            STORE_B(cur ^ 1);
        }
        __syncthreads();
    }

    // Epilogue
#pragma unroll
    for (int i = 0; i < 8; i++) {
        const int r = row0 + ty * 8 + i;
        float* crow = Cb + (size_t)r * N;
#pragma unroll
        for (int j = 0; j < 8; j += 4) {
            const int c = col0 + tx * 8 + j;
            float4 v;
            v.x = acc[i][j + 0];
            v.y = acc[i][j + 1];
            v.z = acc[i][j + 2];
            v.w = acc[i][j + 3];
            if (EPI != 0) {
                v.x += bias[c + 0];
                v.y += bias[c + 1];
                v.z += bias[c + 2];
                v.w += bias[c + 3];
            }
            if (EPI == 1) {
                v.x = fmaxf(v.x, 0.0f);
                v.y = fmaxf(v.y, 0.0f);
                v.z = fmaxf(v.z, 0.0f);
                v.w = fmaxf(v.w, 0.0f);
            }
            if (EPI == 2) {
                v.x = v.x > 0.0f ? v.x : alpha[c + 0] * v.x;
                v.y = v.y > 0.0f ? v.y : alpha[c + 1] * v.y;
                v.z = v.z > 0.0f ? v.z : alpha[c + 2] * v.z;
                v.w = v.w > 0.0f ? v.w : alpha[c + 3] * v.w;
            }
            *reinterpret_cast<float4*>(crow + c) = v;
        }
    }
#undef FETCH_A
#undef FETCH_B
#undef STORE_A
#undef STORE_B
}

// ---------------------------------------------------------------------------
// Final classifier: out[r, 0:2] = h[r, :] @ cW2[256,2] + cb2
// ---------------------------------------------------------------------------
__global__ void cls2_kernel(const float* __restrict__ h, const float* __restrict__ W,
                            const float* __restrict__ bvec, float* __restrict__ out, int M)
{
    __shared__ float Ws[512];
    const int tid = threadIdx.x;
    for (int i = tid; i < 512; i += blockDim.x) Ws[i] = W[i];
    __syncthreads();

    const int r = blockIdx.x * blockDim.x + tid;
    if (r >= M) return;
    const float4* hr = reinterpret_cast<const float4*>(h + (size_t)r * 256);
    float s0 = bvec[0];
    float s1 = bvec[1];
#pragma unroll 8
    for (int k4 = 0; k4 < 64; k4++) {
        float4 v = hr[k4];
        const int k = k4 * 4;
        s0 = fmaf(v.x, Ws[(k + 0) * 2 + 0], s0);
        s1 = fmaf(v.x, Ws[(k + 0) * 2 + 1], s1);
        s0 = fmaf(v.y, Ws[(k + 1) * 2 + 0], s0);
        s1 = fmaf(v.y, Ws[(k + 1) * 2 + 1], s1);
        s0 = fmaf(v.z, Ws[(k + 2) * 2 + 0], s0);
        s1 = fmaf(v.z, Ws[(k + 2) * 2 + 1], s1);
        s0 = fmaf(v.w, Ws[(k + 3) * 2 + 0], s0);
        s1 = fmaf(v.w, Ws[(k + 3) * 2 + 1], s1);
    }
    out[(size_t)r * 2 + 0] = s0;
    out[(size_t)r * 2 + 1] = s1;
}

// ---------------------------------------------------------------------------
extern "C" void kernel_launch(void* const* d_in, const int* in_sizes, int n_in,
                              void* d_out, int out_size)
{
    const float* x    = (const float*)d_in[0];   // [32,1024,256]
    const float* adj  = (const float*)d_in[1];   // [32,1024,1024]
    const float* W1   = (const float*)d_in[2];   // [512,512]
    const float* b1   = (const float*)d_in[3];
    const float* W2   = (const float*)d_in[4];   // [1024,512]
    const float* b2   = (const float*)d_in[5];
    const float* W3   = (const float*)d_in[6];   // [1024,256]
    const float* b3   = (const float*)d_in[7];
    const float* W4   = (const float*)d_in[8];   // [512,256]
    const float* b4   = (const float*)d_in[9];
    const float* cW1  = (const float*)d_in[10];  // [256,256]
    const float* cb1  = (const float*)d_in[11];
    const float* alp  = (const float*)d_in[12];  // [256]
    const float* cW2  = (const float*)d_in[13];  // [256,2]
    const float* cb2  = (const float*)d_in[14];
    float* out = (float*)d_out;                  // [32,1024,2]

    float *agg, *h0, *h1;
    cudaGetSymbolAddress((void**)&agg, g_agg);
    cudaGetSymbolAddress((void**)&h0, g_h0);
    cudaGetSymbolAddress((void**)&h1, g_h1);

    const int NB = 32, NN = 1024;
    const long aS = (long)NN * NN;  // adj batch stride
    dim3 blk(256);

    // ---- Layer 1: agg = adj @ x (d=256) ; h0 = relu([x|agg] @ W1 + b1), out 512
    gemm_kernel<0><<<dim3(2, 8, NB), blk>>>(adj, adj, 1024, x, nullptr, nullptr, agg,
                                            1024, 256, 1024, aS, (long)NN * 256, (long)NN * 256);
    gemm_kernel<1><<<dim3(4, 256, 1), blk>>>(x, agg, 256, W1, b1, nullptr, h0,
                                             32768, 512, 512, 0, 0, 0);

    // ---- Layer 2: agg = adj @ h0 (d=512) ; h1 = relu([h0|agg] @ W2 + b2), out 512
    gemm_kernel<0><<<dim3(4, 8, NB), blk>>>(adj, adj, 1024, h0, nullptr, nullptr, agg,
                                            1024, 512, 1024, aS, (long)NN * 512, (long)NN * 512);
    gemm_kernel<1><<<dim3(4, 256, 1), blk>>>(h0, agg, 512, W2, b2, nullptr, h1,
                                             32768, 512, 1024, 0, 0, 0);

    // ---- Layer 3: agg = adj @ h1 (d=512) ; h0 = relu([h1|agg] @ W3 + b3), out 256
    gemm_kernel<0><<<dim3(4, 8, NB), blk>>>(adj, adj, 1024, h1, nullptr, nullptr, agg,
                                            1024, 512, 1024, aS, (long)NN * 512, (long)NN * 512);
    gemm_kernel<1><<<dim3(2, 256, 1), blk>>>(h1, agg, 512, W3, b3, nullptr, h0,
                                             32768, 256, 1024, 0, 0, 0);

    // ---- Layer 4: agg = adj @ h0 (d=256) ; h1 = relu([h0|agg] @ W4 + b4), out 256
    gemm_kernel<0><<<dim3(2, 8, NB), blk>>>(adj, adj, 1024, h0, nullptr, nullptr, agg,
                                            1024, 256, 1024, aS, (long)NN * 256, (long)NN * 256);
    gemm_kernel<1><<<dim3(2, 256, 1), blk>>>(h0, agg, 256, W4, b4, nullptr, h1,
                                             32768, 256, 512, 0, 0, 0);

    // ---- Classifier: h0 = prelu(h1 @ cW1 + cb1) ; out = h0 @ cW2 + cb2
    gemm_kernel<2><<<dim3(2, 256, 1), blk>>>(h1, h1, 256, cW1, cb1, alp, h0,
                                             32768, 256, 256, 0, 0, 0);
    cls2_kernel<<<dim3(128), blk>>>(h0, cW2, cb2, out, 32768);
}